// round 13
// baseline (speedup 1.0000x reference)
#include <cuda_runtime.h>
#include <cuda_fp16.h>

#define N_NODES 100000
#define N_EDGES 1600000
#define IN_F 128
#define H_F 64
#define OUT_F 32
#define CAP 96        // fixed bucket capacity; P(deg>96) ~ 1e-40 for E/N=16

// ---------------- scratch (device globals: no allocation allowed) ----------
__device__ int    d_cnt      [N_NODES];            // zero at entry (invariant)
__device__ float  d_dinv     [N_NODES];
__device__ int    d_srcsorted[N_NODES * CAP];      // bucketed src lists (38.4MB)
__device__ __half d_g1       [N_NODES * H_F];      // UNSCALED L1 transform (fp16)
__device__ float  d_h1       [N_NODES * H_F];      // relu(dinv*agg + b1)
__device__ __half d_g2       [N_NODES * OUT_F];    // dinv-scaled L2 transform

// ---------------- packed fp32x2 helpers (FFMA2) ------------------------------
__device__ __forceinline__ unsigned long long dup_f32(float x) {
    unsigned long long r;
    asm("mov.b64 %0, {%1, %1};" : "=l"(r) : "f"(x));
    return r;
}
__device__ __forceinline__ void fma2(unsigned long long& d,
                                     unsigned long long a,
                                     unsigned long long b) {
    asm("fma.rn.f32x2 %0, %1, %2, %3;" : "=l"(d) : "l"(a), "l"(b), "l"(d));
}
__device__ __forceinline__ float2 unpack_f32x2(unsigned long long v) {
    float2 f;
    asm("mov.b64 {%0, %1}, %2;" : "=f"(f.x), "=f"(f.y) : "l"(v));
    return f;
}

// ---------------- ONE-PASS bucket fill + count (replaces count/scan/fill) ---
// Requires d_cnt == 0 at entry: true initially (zero-init) and re-established
// by gather2_kernel every call.
__global__ void fillcount_kernel(const int* __restrict__ ei) {
    int t = blockIdx.x * blockDim.x + threadIdx.x;
    if (t < N_EDGES / 4) {
        int4 s = reinterpret_cast<const int4*>(ei)[t];
        int4 d = reinterpret_cast<const int4*>(ei + N_EDGES)[t];
        int p0 = atomicAdd(&d_cnt[d.x], 1);
        int p1 = atomicAdd(&d_cnt[d.y], 1);
        int p2 = atomicAdd(&d_cnt[d.z], 1);
        int p3 = atomicAdd(&d_cnt[d.w], 1);
        if (p0 < CAP) d_srcsorted[d.x * CAP + p0] = s.x;
        if (p1 < CAP) d_srcsorted[d.y * CAP + p1] = s.y;
        if (p2 < CAP) d_srcsorted[d.z * CAP + p2] = s.z;
        if (p3 < CAP) d_srcsorted[d.w * CAP + p3] = s.w;
    }
}

// ---------------- dinv[i] = rsqrt(deg_in + 1) --------------------------------
__global__ void dinv_kernel() {
    int i = blockIdx.x * blockDim.x + threadIdx.x;
    if (i < N_NODES) d_dinv[i] = rsqrtf((float)(d_cnt[i] + 1));
}

// ---------------- GEMM1: g1[i,c] = fp16( x[i,:] . W1[c,:] ) — NO dinv -------
// (dinv-free so it overlaps the bucket build on the fork.)
__global__ void gemm1_kernel(const float* __restrict__ x,
                             const float* __restrict__ W1) {
    __shared__ float xs[128 * 68];   // xs[k][r]
    __shared__ float Wt[32 * 68];    // Wt[kl][c]
    const int tid = threadIdx.x;
    const int row0 = blockIdx.x * 64;

    for (int idx = tid; idx < 64 * 128; idx += 256) {
        int r = idx >> 7, k = idx & 127;
        int row = row0 + r;
        xs[k * 68 + r] = (row < N_NODES) ? x[row * IN_F + k] : 0.f;
    }

    const int r0 = (tid >> 4) * 4;
    const int c0 = (tid & 15) * 4;
    unsigned long long acc2[4][2] = {};   // [row][colpair]

    for (int kc = 0; kc < 4; ++kc) {
        __syncthreads();
        for (int idx = tid; idx < 64 * 32; idx += 256) {
            int c = idx >> 5, kl = idx & 31;
            Wt[kl * 68 + c] = W1[c * IN_F + kc * 32 + kl];
        }
        __syncthreads();
        #pragma unroll
        for (int kl = 0; kl < 32; ++kl) {
            int k = kc * 32 + kl;
            float4 xv = *reinterpret_cast<const float4*>(&xs[k * 68 + r0]);
            const unsigned long long* wp =
                reinterpret_cast<const unsigned long long*>(&Wt[kl * 68 + c0]);
            unsigned long long w0 = wp[0];
            unsigned long long w1 = wp[1];
            unsigned long long x0 = dup_f32(xv.x);
            unsigned long long x1 = dup_f32(xv.y);
            unsigned long long x2 = dup_f32(xv.z);
            unsigned long long x3 = dup_f32(xv.w);
            fma2(acc2[0][0], x0, w0); fma2(acc2[0][1], x0, w1);
            fma2(acc2[1][0], x1, w0); fma2(acc2[1][1], x1, w1);
            fma2(acc2[2][0], x2, w0); fma2(acc2[2][1], x2, w1);
            fma2(acc2[3][0], x3, w0); fma2(acc2[3][1], x3, w1);
        }
    }

    #pragma unroll
    for (int i = 0; i < 4; ++i) {
        int row = row0 + r0 + i;
        if (row < N_NODES) {
            float2 a = unpack_f32x2(acc2[i][0]);
            float2 b = unpack_f32x2(acc2[i][1]);
            __half2 p0 = __floats2half2_rn(a.x, a.y);
            __half2 p1 = __floats2half2_rn(b.x, b.y);
            __half2* dst = reinterpret_cast<__half2*>(&d_g1[row * H_F + c0]);
            dst[0] = p0;
            dst[1] = p1;
        }
    }
}

// ---------------- gather L1: h = relu(dinv[i]*(Σ dinv[s]*g1[s]) + b1) -------
// One warp per dst node; bucket rows are contiguous at warp*CAP.
__global__ void gather1_kernel(const float* __restrict__ b1) {
    int warp = (blockIdx.x * blockDim.x + threadIdx.x) >> 5;
    int lane = threadIdx.x & 31;
    if (warp >= N_NODES) return;

    const __half2* g = reinterpret_cast<const __half2*>(d_g1);
    const float di = d_dinv[warp];
    float2 sv = __half22float2(g[warp * 32 + lane]);
    float2 acc;                                      // self loop: dinv[i]*g1[i]
    acc.x = di * sv.x;
    acc.y = di * sv.y;

    int deg = d_cnt[warp];
    if (deg > CAP) deg = CAP;
    int e = warp * CAP;
    const int end = e + deg;

    for (; e + 4 <= end; e += 4) {
        int s0 = __ldg(&d_srcsorted[e + 0]);
        int s1 = __ldg(&d_srcsorted[e + 1]);
        int s2 = __ldg(&d_srcsorted[e + 2]);
        int s3 = __ldg(&d_srcsorted[e + 3]);
        float  d0 = __ldg(&d_dinv[s0]);
        float  d1 = __ldg(&d_dinv[s1]);
        float  d2 = __ldg(&d_dinv[s2]);
        float  d3 = __ldg(&d_dinv[s3]);
        float2 v0 = __half22float2(__ldg(&g[s0 * 32 + lane]));
        float2 v1 = __half22float2(__ldg(&g[s1 * 32 + lane]));
        float2 v2 = __half22float2(__ldg(&g[s2 * 32 + lane]));
        float2 v3 = __half22float2(__ldg(&g[s3 * 32 + lane]));
        acc.x = fmaf(d0, v0.x, fmaf(d1, v1.x, fmaf(d2, v2.x, fmaf(d3, v3.x, acc.x))));
        acc.y = fmaf(d0, v0.y, fmaf(d1, v1.y, fmaf(d2, v2.y, fmaf(d3, v3.y, acc.y))));
    }
    for (; e < end; ++e) {
        int s = __ldg(&d_srcsorted[e]);
        float ds = __ldg(&d_dinv[s]);
        float2 v = __half22float2(__ldg(&g[s * 32 + lane]));
        acc.x = fmaf(ds, v.x, acc.x);
        acc.y = fmaf(ds, v.y, acc.y);
    }

    float2 b = __ldg(reinterpret_cast<const float2*>(b1) + lane);
    float2 h;
    h.x = fmaxf(fmaf(di, acc.x, b.x), 0.f);
    h.y = fmaxf(fmaf(di, acc.y, b.y), 0.f);
    reinterpret_cast<float2*>(d_h1)[warp * 32 + lane] = h;
}

// ---------------- GEMM2: g2[i,c] = fp16( dinv[i] * (h1[i,:] . W2[c,:]) ) -----
__global__ void gemm2_kernel(const float* __restrict__ W2) {
    __shared__ float ht[64 * 66];    // ht[j][r]
    __shared__ float Wt[64 * 36];    // Wt[j][c]
    const int tid = threadIdx.x;
    const int row0 = blockIdx.x * 64;

    for (int idx = tid; idx < 64 * 64; idx += 256) {
        int r = idx >> 6, j = idx & 63;
        int row = row0 + r;
        ht[j * 66 + r] = (row < N_NODES) ? d_h1[row * H_F + j] : 0.f;
    }
    for (int idx = tid; idx < 32 * 64; idx += 256) {
        int c = idx >> 6, j = idx & 63;
        Wt[j * 36 + c] = W2[c * H_F + j];
    }
    __syncthreads();

    const int r0 = (tid >> 3) * 2;
    const int c0 = (tid & 7) * 4;
    unsigned long long acc2[2][2] = {};

    #pragma unroll
    for (int j = 0; j < 64; ++j) {
        float2 hv = *reinterpret_cast<const float2*>(&ht[j * 66 + r0]);
        const unsigned long long* wp =
            reinterpret_cast<const unsigned long long*>(&Wt[j * 36 + c0]);
        unsigned long long w0 = wp[0];
        unsigned long long w1 = wp[1];
        unsigned long long h0 = dup_f32(hv.x);
        unsigned long long h1 = dup_f32(hv.y);
        fma2(acc2[0][0], h0, w0); fma2(acc2[0][1], h0, w1);
        fma2(acc2[1][0], h1, w0); fma2(acc2[1][1], h1, w1);
    }

    #pragma unroll
    for (int i = 0; i < 2; ++i) {
        int row = row0 + r0 + i;
        if (row < N_NODES) {
            float di = d_dinv[row];
            float2 a = unpack_f32x2(acc2[i][0]);
            float2 b = unpack_f32x2(acc2[i][1]);
            __half2 p0 = __floats2half2_rn(a.x * di, a.y * di);
            __half2 p1 = __floats2half2_rn(b.x * di, b.y * di);
            __half2* dst = reinterpret_cast<__half2*>(&d_g2[row * OUT_F + c0]);
            dst[0] = p0;
            dst[1] = p1;
        }
    }
}

// ---------------- gather L2 + bias -> output; re-zeroes d_cnt ----------------
__global__ void gather2_kernel(const float* __restrict__ b2,
                               float* __restrict__ out) {
    int warp = (blockIdx.x * blockDim.x + threadIdx.x) >> 5;
    int lane = threadIdx.x & 31;
    if (warp >= N_NODES) return;

    float acc = __half2float(d_g2[warp * OUT_F + lane]);   // self loop
    int deg = d_cnt[warp];
    if (deg > CAP) deg = CAP;
    if (lane == 0) d_cnt[warp] = 0;          // restore invariant for next call
    int e = warp * CAP;
    const int end = e + deg;

    for (; e + 8 <= end; e += 8) {
        int s0 = __ldg(&d_srcsorted[e + 0]);
        int s1 = __ldg(&d_srcsorted[e + 1]);
        int s2 = __ldg(&d_srcsorted[e + 2]);
        int s3 = __ldg(&d_srcsorted[e + 3]);
        int s4 = __ldg(&d_srcsorted[e + 4]);
        int s5 = __ldg(&d_srcsorted[e + 5]);
        int s6 = __ldg(&d_srcsorted[e + 6]);
        int s7 = __ldg(&d_srcsorted[e + 7]);
        float v0 = __half2float(__ldg(&d_g2[s0 * OUT_F + lane]));
        float v1 = __half2float(__ldg(&d_g2[s1 * OUT_F + lane]));
        float v2 = __half2float(__ldg(&d_g2[s2 * OUT_F + lane]));
        float v3 = __half2float(__ldg(&d_g2[s3 * OUT_F + lane]));
        float v4 = __half2float(__ldg(&d_g2[s4 * OUT_F + lane]));
        float v5 = __half2float(__ldg(&d_g2[s5 * OUT_F + lane]));
        float v6 = __half2float(__ldg(&d_g2[s6 * OUT_F + lane]));
        float v7 = __half2float(__ldg(&d_g2[s7 * OUT_F + lane]));
        acc += ((v0 + v1) + (v2 + v3)) + ((v4 + v5) + (v6 + v7));
    }
    for (; e < end; ++e) {
        int s = __ldg(&d_srcsorted[e]);
        acc += __half2float(__ldg(&d_g2[s * OUT_F + lane]));
    }

    out[warp * OUT_F + lane] = fmaf(d_dinv[warp], acc, __ldg(&b2[lane]));
}

extern "C" void kernel_launch(void* const* d_in, const int* in_sizes, int n_in,
                              void* d_out, int out_size) {
    const float* x  = (const float*)d_in[0];
    const int*   ei = (const int*)  d_in[1];
    const float* W1 = (const float*)d_in[2];
    const float* b1 = (const float*)d_in[3];
    const float* W2 = (const float*)d_in[4];
    const float* b2 = (const float*)d_in[5];
    float* out = (float*)d_out;

    // Fork: one-pass bucket build (latency/atomic-bound) on side stream,
    // gemm1 (FMA-bound) on the main stream.
    cudaStream_t s;
    cudaStreamCreateWithFlags(&s, cudaStreamNonBlocking);
    cudaEvent_t ev_fork, ev_join;
    cudaEventCreateWithFlags(&ev_fork, cudaEventDisableTiming);
    cudaEventCreateWithFlags(&ev_join, cudaEventDisableTiming);

    cudaEventRecord(ev_fork, 0);
    cudaStreamWaitEvent(s, ev_fork, 0);

    // side stream: bucket fill (+count) then dinv
    fillcount_kernel<<<(N_EDGES / 4 + 255) / 256, 256, 0, s>>>(ei);
    dinv_kernel     <<<(N_NODES + 255) / 256, 256, 0, s>>>();
    cudaEventRecord(ev_join, s);

    // main stream: gemm1 (independent of buckets/dinv)
    gemm1_kernel <<<(N_NODES + 63) / 64, 256>>>(x, W1);

    // join, then the dependent tail
    cudaStreamWaitEvent(0, ev_join, 0);
    gather1_kernel<<<(N_NODES * 32 + 255) / 256, 256>>>(b1);
    gemm2_kernel  <<<(N_NODES + 63) / 64, 256>>>(W2);
    gather2_kernel<<<(N_NODES * 32 + 255) / 256, 256>>>(b2, out);
    // NOTE: stream/event handles intentionally not destroyed — destroying
    // capture-participating handles mid-capture is hazardous; kernel_launch
    // is invoked only a handful of times, so the leak is bounded, host-side.
}

// round 14
// speedup vs baseline: 1.5255x; 1.5255x over previous
#include <cuda_runtime.h>
#include <cuda_fp16.h>

#define N_NODES 100000
#define N_EDGES 1600000
#define IN_F 128
#define H_F 64
#define OUT_F 32
#define SCAN_BLK 1024
#define NB_SCAN ((N_NODES + SCAN_BLK - 1) / SCAN_BLK)   // 98

// ---------------- scratch (device globals: no allocation allowed) ----------
__device__ int    d_cnt      [N_NODES + 32];       // zero at entry (invariant)
__device__ float  d_dinv     [N_NODES];
__device__ int    d_rowptr   [N_NODES + 1];
__device__ int    d_cursor   [N_NODES];
__device__ int    d_bsum     [128];
__device__ int    d_srcsorted[N_EDGES];            // CSR-by-dst src list (6.4MB)
__device__ __half d_g1       [N_NODES * H_F];      // UNSCALED L1 transform (fp16)
__device__ float  d_h1       [N_NODES * H_F];      // relu(dinv*agg + b1)
__device__ __half d_g2       [N_NODES * OUT_F];    // dinv-scaled L2 transform

// ---------------- packed fp32x2 helpers (FFMA2) ------------------------------
__device__ __forceinline__ unsigned long long dup_f32(float x) {
    unsigned long long r;
    asm("mov.b64 %0, {%1, %1};" : "=l"(r) : "f"(x));
    return r;
}
__device__ __forceinline__ void fma2(unsigned long long& d,
                                     unsigned long long a,
                                     unsigned long long b) {
    asm("fma.rn.f32x2 %0, %1, %2, %3;" : "=l"(d) : "l"(a), "l"(b), "l"(d));
}
__device__ __forceinline__ float2 unpack_f32x2(unsigned long long v) {
    float2 f;
    asm("mov.b64 {%0, %1}, %2;" : "=f"(f.x), "=f"(f.y) : "l"(v));
    return f;
}

// ---------------- degree counting: 8 edges / thread (high MLP, few warps) ---
// Low warp footprint (782 blocks) so it co-resides with gemm1 on each SM.
// Requires d_cnt == 0 at entry: true initially and re-set by scan_c.
__global__ void count_kernel(const int* __restrict__ ei) {
    int t = blockIdx.x * blockDim.x + threadIdx.x;
    if (t < N_EDGES / 8) {
        const int4* dp = reinterpret_cast<const int4*>(ei + N_EDGES);
        int4 a = dp[t * 2 + 0];
        int4 b = dp[t * 2 + 1];
        atomicAdd(&d_cnt[a.x], 1);
        atomicAdd(&d_cnt[a.y], 1);
        atomicAdd(&d_cnt[a.z], 1);
        atomicAdd(&d_cnt[a.w], 1);
        atomicAdd(&d_cnt[b.x], 1);
        atomicAdd(&d_cnt[b.y], 1);
        atomicAdd(&d_cnt[b.z], 1);
        atomicAdd(&d_cnt[b.w], 1);
    }
}

// ---------------- scan A: block-local exclusive scan + block sums -----------
__global__ void scan_a_kernel() {
    __shared__ int wpre[32];
    const int tid  = threadIdx.x;
    const int lane = tid & 31;
    const int wid  = tid >> 5;
    const int gid  = blockIdx.x * SCAN_BLK + tid;
    int v = (gid < N_NODES) ? d_cnt[gid] : 0;

    int inc = v;
    #pragma unroll
    for (int o = 1; o < 32; o <<= 1) {
        int t = __shfl_up_sync(0xffffffffu, inc, o);
        if (lane >= o) inc += t;
    }
    if (lane == 31) wpre[wid] = inc;
    __syncthreads();
    if (wid == 0) {
        int s = wpre[lane];
        #pragma unroll
        for (int o = 1; o < 32; o <<= 1) {
            int t = __shfl_up_sync(0xffffffffu, s, o);
            if (lane >= o) s += t;
        }
        wpre[lane] = s;                       // inclusive warp-sum scan
    }
    __syncthreads();
    int base = (wid > 0) ? wpre[wid - 1] : 0;
    if (gid < N_NODES) d_rowptr[gid] = base + inc - v;   // block-local exclusive
    if (tid == SCAN_BLK - 1) d_bsum[blockIdx.x] = wpre[31];   // raw block total
}

// ---------------- scan C: globalize + cursor + dinv + cnt re-zero -----------
__global__ void scan_c_kernel() {
    __shared__ int base;
    const int tid = threadIdx.x;
    const int gid = blockIdx.x * 256 + tid;
    const int chunk = blockIdx.x >> 2;      // # scan_a blocks before this range
    if (tid == 0) base = 0;
    __syncthreads();
    if (tid < chunk) atomicAdd(&base, d_bsum[tid]);
    __syncthreads();
    if (gid < N_NODES) {
        int r = d_rowptr[gid] + base;
        d_rowptr[gid] = r;
        d_cursor[gid] = r;
        d_dinv[gid] = rsqrtf((float)(d_cnt[gid] + 1));   // +1 self loop
        d_cnt[gid] = 0;                      // re-zero for next replay
    }
    if (gid == 0) d_rowptr[N_NODES] = N_EDGES;
}

// ---------------- CSR fill: 8 edges / thread (high MLP, few warps) ----------
__global__ void fill_kernel(const int* __restrict__ ei) {
    int t = blockIdx.x * blockDim.x + threadIdx.x;
    if (t < N_EDGES / 8) {
        const int4* sp = reinterpret_cast<const int4*>(ei);
        const int4* dp = reinterpret_cast<const int4*>(ei + N_EDGES);
        int4 s0 = sp[t * 2 + 0];
        int4 s1 = sp[t * 2 + 1];
        int4 d0 = dp[t * 2 + 0];
        int4 d1 = dp[t * 2 + 1];
        d_srcsorted[atomicAdd(&d_cursor[d0.x], 1)] = s0.x;
        d_srcsorted[atomicAdd(&d_cursor[d0.y], 1)] = s0.y;
        d_srcsorted[atomicAdd(&d_cursor[d0.z], 1)] = s0.z;
        d_srcsorted[atomicAdd(&d_cursor[d0.w], 1)] = s0.w;
        d_srcsorted[atomicAdd(&d_cursor[d1.x], 1)] = s1.x;
        d_srcsorted[atomicAdd(&d_cursor[d1.y], 1)] = s1.y;
        d_srcsorted[atomicAdd(&d_cursor[d1.z], 1)] = s1.z;
        d_srcsorted[atomicAdd(&d_cursor[d1.w], 1)] = s1.w;
    }
}

// ---------------- GEMM1: g1[i,c] = fp16( x[i,:] . W1[c,:] ) — NO dinv -------
// (dinv-free so it overlaps the CSR build on the fork.)
__global__ void gemm1_kernel(const float* __restrict__ x,
                             const float* __restrict__ W1) {
    __shared__ float xs[128 * 68];   // xs[k][r]
    __shared__ float Wt[32 * 68];    // Wt[kl][c]
    const int tid = threadIdx.x;
    const int row0 = blockIdx.x * 64;

    for (int idx = tid; idx < 64 * 128; idx += 256) {
        int r = idx >> 7, k = idx & 127;
        int row = row0 + r;
        xs[k * 68 + r] = (row < N_NODES) ? x[row * IN_F + k] : 0.f;
    }

    const int r0 = (tid >> 4) * 4;
    const int c0 = (tid & 15) * 4;
    unsigned long long acc2[4][2] = {};   // [row][colpair]

    for (int kc = 0; kc < 4; ++kc) {
        __syncthreads();
        for (int idx = tid; idx < 64 * 32; idx += 256) {
            int c = idx >> 5, kl = idx & 31;
            Wt[kl * 68 + c] = W1[c * IN_F + kc * 32 + kl];
        }
        __syncthreads();
        #pragma unroll
        for (int kl = 0; kl < 32; ++kl) {
            int k = kc * 32 + kl;
            float4 xv = *reinterpret_cast<const float4*>(&xs[k * 68 + r0]);
            const unsigned long long* wp =
                reinterpret_cast<const unsigned long long*>(&Wt[kl * 68 + c0]);
            unsigned long long w0 = wp[0];
            unsigned long long w1 = wp[1];
            unsigned long long x0 = dup_f32(xv.x);
            unsigned long long x1 = dup_f32(xv.y);
            unsigned long long x2 = dup_f32(xv.z);
            unsigned long long x3 = dup_f32(xv.w);
            fma2(acc2[0][0], x0, w0); fma2(acc2[0][1], x0, w1);
            fma2(acc2[1][0], x1, w0); fma2(acc2[1][1], x1, w1);
            fma2(acc2[2][0], x2, w0); fma2(acc2[2][1], x2, w1);
            fma2(acc2[3][0], x3, w0); fma2(acc2[3][1], x3, w1);
        }
    }

    #pragma unroll
    for (int i = 0; i < 4; ++i) {
        int row = row0 + r0 + i;
        if (row < N_NODES) {
            float2 a = unpack_f32x2(acc2[i][0]);
            float2 b = unpack_f32x2(acc2[i][1]);
            __half2 p0 = __floats2half2_rn(a.x, a.y);
            __half2 p1 = __floats2half2_rn(b.x, b.y);
            __half2* dst = reinterpret_cast<__half2*>(&d_g1[row * H_F + c0]);
            dst[0] = p0;
            dst[1] = p1;
        }
    }
}

// ---------------- gather L1: h = relu(dinv[i]*(Σ dinv[s]*g1[s]) + b1) -------
// One warp per dst node; 8-wide edge unroll for MLP; per-edge dinv[src] FMA.
__global__ void gather1_kernel(const float* __restrict__ b1) {
    int warp = (blockIdx.x * blockDim.x + threadIdx.x) >> 5;
    int lane = threadIdx.x & 31;
    if (warp >= N_NODES) return;

    const __half2* g = reinterpret_cast<const __half2*>(d_g1);
    const int* __restrict__ ss = d_srcsorted;
    const float* __restrict__ dv = d_dinv;

    const float di = dv[warp];
    float2 sv = __half22float2(g[warp * 32 + lane]);
    float2 acc;                                      // self loop: dinv[i]*g1[i]
    acc.x = di * sv.x;
    acc.y = di * sv.y;
    int e = d_rowptr[warp];
    const int end = d_rowptr[warp + 1];

    for (; e + 8 <= end; e += 8) {
        int s0 = __ldg(&ss[e + 0]);
        int s1 = __ldg(&ss[e + 1]);
        int s2 = __ldg(&ss[e + 2]);
        int s3 = __ldg(&ss[e + 3]);
        int s4 = __ldg(&ss[e + 4]);
        int s5 = __ldg(&ss[e + 5]);
        int s6 = __ldg(&ss[e + 6]);
        int s7 = __ldg(&ss[e + 7]);
        float  e0 = __ldg(&dv[s0]);
        float  e1 = __ldg(&dv[s1]);
        float  e2 = __ldg(&dv[s2]);
        float  e3 = __ldg(&dv[s3]);
        float  e4 = __ldg(&dv[s4]);
        float  e5 = __ldg(&dv[s5]);
        float  e6 = __ldg(&dv[s6]);
        float  e7 = __ldg(&dv[s7]);
        float2 v0 = __half22float2(__ldg(&g[s0 * 32 + lane]));
        float2 v1 = __half22float2(__ldg(&g[s1 * 32 + lane]));
        float2 v2 = __half22float2(__ldg(&g[s2 * 32 + lane]));
        float2 v3 = __half22float2(__ldg(&g[s3 * 32 + lane]));
        float2 v4 = __half22float2(__ldg(&g[s4 * 32 + lane]));
        float2 v5 = __half22float2(__ldg(&g[s5 * 32 + lane]));
        float2 v6 = __half22float2(__ldg(&g[s6 * 32 + lane]));
        float2 v7 = __half22float2(__ldg(&g[s7 * 32 + lane]));
        float2 p, q;
        p.x = fmaf(e0, v0.x, fmaf(e1, v1.x, fmaf(e2, v2.x, e3 * v3.x)));
        p.y = fmaf(e0, v0.y, fmaf(e1, v1.y, fmaf(e2, v2.y, e3 * v3.y)));
        q.x = fmaf(e4, v4.x, fmaf(e5, v5.x, fmaf(e6, v6.x, e7 * v7.x)));
        q.y = fmaf(e4, v4.y, fmaf(e5, v5.y, fmaf(e6, v6.y, e7 * v7.y)));
        acc.x += p.x + q.x;
        acc.y += p.y + q.y;
    }
    for (; e < end; ++e) {
        int s = __ldg(&ss[e]);
        float ds = __ldg(&dv[s]);
        float2 v = __half22float2(__ldg(&g[s * 32 + lane]));
        acc.x = fmaf(ds, v.x, acc.x);
        acc.y = fmaf(ds, v.y, acc.y);
    }

    float2 b = __ldg(reinterpret_cast<const float2*>(b1) + lane);
    float2 h;
    h.x = fmaxf(fmaf(di, acc.x, b.x), 0.f);
    h.y = fmaxf(fmaf(di, acc.y, b.y), 0.f);
    reinterpret_cast<float2*>(d_h1)[warp * 32 + lane] = h;
}

// ---------------- GEMM2: g2[i,c] = fp16( dinv[i] * (h1[i,:] . W2[c,:]) ) -----
__global__ void gemm2_kernel(const float* __restrict__ W2) {
    __shared__ float ht[64 * 66];    // ht[j][r]
    __shared__ float Wt[64 * 36];    // Wt[j][c]
    const int tid = threadIdx.x;
    const int row0 = blockIdx.x * 64;

    for (int idx = tid; idx < 64 * 64; idx += 256) {
        int r = idx >> 6, j = idx & 63;
        int row = row0 + r;
        ht[j * 66 + r] = (row < N_NODES) ? d_h1[row * H_F + j] : 0.f;
    }
    for (int idx = tid; idx < 32 * 64; idx += 256) {
        int c = idx >> 6, j = idx & 63;
        Wt[j * 36 + c] = W2[c * H_F + j];
    }
    __syncthreads();

    const int r0 = (tid >> 3) * 2;
    const int c0 = (tid & 7) * 4;
    unsigned long long acc2[2][2] = {};

    #pragma unroll
    for (int j = 0; j < 64; ++j) {
        float2 hv = *reinterpret_cast<const float2*>(&ht[j * 66 + r0]);
        const unsigned long long* wp =
            reinterpret_cast<const unsigned long long*>(&Wt[j * 36 + c0]);
        unsigned long long w0 = wp[0];
        unsigned long long w1 = wp[1];
        unsigned long long h0 = dup_f32(hv.x);
        unsigned long long h1 = dup_f32(hv.y);
        fma2(acc2[0][0], h0, w0); fma2(acc2[0][1], h0, w1);
        fma2(acc2[1][0], h1, w0); fma2(acc2[1][1], h1, w1);
    }

    #pragma unroll
    for (int i = 0; i < 2; ++i) {
        int row = row0 + r0 + i;
        if (row < N_NODES) {
            float di = d_dinv[row];
            float2 a = unpack_f32x2(acc2[i][0]);
            float2 b = unpack_f32x2(acc2[i][1]);
            __half2 p0 = __floats2half2_rn(a.x * di, a.y * di);
            __half2 p1 = __floats2half2_rn(b.x * di, b.y * di);
            __half2* dst = reinterpret_cast<__half2*>(&d_g2[row * OUT_F + c0]);
            dst[0] = p0;
            dst[1] = p1;
        }
    }
}

// ---------------- gather L2 (CSR, fp16) + bias -> output ---------------------
__global__ void gather2_kernel(const float* __restrict__ b2,
                               float* __restrict__ out) {
    int warp = (blockIdx.x * blockDim.x + threadIdx.x) >> 5;
    int lane = threadIdx.x & 31;
    if (warp >= N_NODES) return;

    float acc = __half2float(d_g2[warp * OUT_F + lane]);   // self loop
    int e = d_rowptr[warp];
    const int end = d_rowptr[warp + 1];

    for (; e + 8 <= end; e += 8) {
        int s0 = __ldg(&d_srcsorted[e + 0]);
        int s1 = __ldg(&d_srcsorted[e + 1]);
        int s2 = __ldg(&d_srcsorted[e + 2]);
        int s3 = __ldg(&d_srcsorted[e + 3]);
        int s4 = __ldg(&d_srcsorted[e + 4]);
        int s5 = __ldg(&d_srcsorted[e + 5]);
        int s6 = __ldg(&d_srcsorted[e + 6]);
        int s7 = __ldg(&d_srcsorted[e + 7]);
        float v0 = __half2float(__ldg(&d_g2[s0 * OUT_F + lane]));
        float v1 = __half2float(__ldg(&d_g2[s1 * OUT_F + lane]));
        float v2 = __half2float(__ldg(&d_g2[s2 * OUT_F + lane]));
        float v3 = __half2float(__ldg(&d_g2[s3 * OUT_F + lane]));
        float v4 = __half2float(__ldg(&d_g2[s4 * OUT_F + lane]));
        float v5 = __half2float(__ldg(&d_g2[s5 * OUT_F + lane]));
        float v6 = __half2float(__ldg(&d_g2[s6 * OUT_F + lane]));
        float v7 = __half2float(__ldg(&d_g2[s7 * OUT_F + lane]));
        acc += ((v0 + v1) + (v2 + v3)) + ((v4 + v5) + (v6 + v7));
    }
    for (; e < end; ++e) {
        int s = __ldg(&d_srcsorted[e]);
        acc += __half2float(__ldg(&d_g2[s * OUT_F + lane]));
    }

    out[warp * OUT_F + lane] = fmaf(d_dinv[warp], acc, __ldg(&b2[lane]));
}

extern "C" void kernel_launch(void* const* d_in, const int* in_sizes, int n_in,
                              void* d_out, int out_size) {
    const float* x  = (const float*)d_in[0];
    const int*   ei = (const int*)  d_in[1];
    const float* W1 = (const float*)d_in[2];
    const float* b1 = (const float*)d_in[3];
    const float* W2 = (const float*)d_in[4];
    const float* b2 = (const float*)d_in[5];
    float* out = (float*)d_out;

    // Fork: CSR build (latency-bound, LOW warp footprint for co-residency)
    // on side stream; gemm1 (FMA-bound) on the main stream.
    cudaStream_t s;
    cudaStreamCreateWithFlags(&s, cudaStreamNonBlocking);
    cudaEvent_t ev_fork, ev_join;
    cudaEventCreateWithFlags(&ev_fork, cudaEventDisableTiming);
    cudaEventCreateWithFlags(&ev_join, cudaEventDisableTiming);

    cudaEventRecord(ev_fork, 0);
    cudaStreamWaitEvent(s, ev_fork, 0);

    // side stream: CSR build chain (count/fill = 8 edges/thread, 782 blocks)
    count_kernel <<<(N_EDGES / 8 + 255) / 256, 256, 0, s>>>(ei);
    scan_a_kernel<<<NB_SCAN, SCAN_BLK, 0, s>>>();
    scan_c_kernel<<<(N_NODES + 255) / 256, 256, 0, s>>>();
    fill_kernel  <<<(N_EDGES / 8 + 255) / 256, 256, 0, s>>>(ei);
    cudaEventRecord(ev_join, s);

    // main stream: gemm1 (independent of CSR/dinv)
    gemm1_kernel <<<(N_NODES + 63) / 64, 256>>>(x, W1);

    // join, then the dependent tail
    cudaStreamWaitEvent(0, ev_join, 0);
    gather1_kernel<<<(N_NODES * 32 + 255) / 256, 256>>>(b1);
    gemm2_kernel  <<<(N_NODES + 63) / 64, 256>>>(W2);
    gather2_kernel<<<(N_NODES * 32 + 255) / 256, 256>>>(b2, out);
    // NOTE: stream/event handles intentionally not destroyed — destroying
    // capture-participating handles mid-capture is hazardous; kernel_launch
    // is invoked only a handful of times, so the leak is bounded, host-side.
}